// round 3
// baseline (speedup 1.0000x reference)
#include <cuda_runtime.h>
#include <math.h>

#define HH 128
#define WW 128
#define SAT_STRIDE 132           // row stride in floats (mult of 4, data at cols 4..131)
#define MAX_PATCH 8192

// Scratch (no allocations allowed): patch coords + reciprocal counts.
__device__ int4  g_coords[MAX_PATCH];
__device__ float g_inv[MAX_PATCH];

// ---------------------------------------------------------------------------
// Kernel 1: patch coordinates, exactly matching the reference's float math.
//   n = i * nrois + r ;  round == rintf (round-half-even == jnp.round)
// ---------------------------------------------------------------------------
__global__ void coords_kernel(const float* __restrict__ roi,
                              int nrois, int patch_num, int p) {
    int n = blockIdx.x * blockDim.x + threadIdx.x;
    int N = nrois * patch_num;
    if (n >= N) return;

    int i = n / nrois;     // patch index within roi
    int r = n % nrois;     // roi index

    float4 rb = reinterpret_cast<const float4*>(roi)[r];
    float xmin = rb.x, ymin = rb.y, xmax = rb.z, ymax = rb.w;

    float ix = (float)(i % p);
    float iy = (float)(i / p);
    float pf = (float)p;

    float wstep = __fdiv_rn(__fadd_rn(xmax, -xmin), pf);
    float hstep = __fdiv_rn(__fadd_rn(ymax, -ymin), pf);

    float ax = __fadd_rn(xmin, __fmul_rn(ix, wstep));
    float ay = __fadd_rn(ymin, __fmul_rn(iy, hstep));

    int x0 = (int)rintf(ax);
    int y0 = (int)rintf(ay);
    int x1 = (int)rintf(__fadd_rn(ax, wstep));
    int y1 = (int)rintf(__fadd_rn(ay, hstep));

    // Reference divides by the RAW (unclamped) count.
    float cnt = (float)((y1 - y0) * (x1 - x0));
    g_inv[n] = 1.0f / fmaxf(cnt, 1.0f);

    // Clamp only for safe SAT indexing.
    x0 = min(max(x0, 0), WW);  x1 = min(max(x1, 0), WW);
    y0 = min(max(y0, 0), HH);  y1 = min(max(y1, 0), HH);
    g_coords[n] = make_int4(x0, y0, x1, y1);
}

// ---------------------------------------------------------------------------
// Kernel 2: one CTA (256 thr) per channel.
//   Phase 1 (fused load + row scan): each warp owns 16 rows. Per row:
//     LDG.128 (lane l -> elems 4l..4l+3), in-register inclusive scan
//     (intra-float4 + __shfl_up warp scan), one conflict-free STS.128 of
//     the scanned row into sat[row][4..131]; sat[row][3] = 0 boundary.
//   Phase 2 (column scan): thread t<128 scans column 4+t down 128 rows
//     (stride-1 across lanes -> conflict-free).
//   Phase 3 (gather): 4 LDS per patch; y0==0 boundary via predicated
//     subtraction (no stored zero row needed).
//   sat[y][4+x] = sum_{y'<=y, x'<=x} fm[y'][x']
// ---------------------------------------------------------------------------
__global__ void __launch_bounds__(256) sat_pool_kernel(
    const float* __restrict__ fm, float* __restrict__ out, int C, int N) {
    extern __shared__ float sat[];   // HH * SAT_STRIDE floats = 67584 B

    const int c    = blockIdx.x;
    const int tid  = threadIdx.x;
    const int warp = tid >> 5;
    const int lane = tid & 31;

    // --- Phase 1: fused load + row prefix scan (all 8 warps active) ---
    const float4* src =
        reinterpret_cast<const float4*>(fm + (size_t)c * HH * WW);
    #pragma unroll 2
    for (int r = warp; r < HH; r += 8) {
        float4 v = src[r * (WW / 4) + lane];
        // intra-float4 inclusive scan
        v.y += v.x; v.z += v.y; v.w += v.z;
        // warp-level inclusive scan of lane totals
        float s = v.w;
        #pragma unroll
        for (int d = 1; d < 32; d <<= 1) {
            float t = __shfl_up_sync(0xffffffffu, s, d);
            if (lane >= d) s += t;
        }
        float excl = s - v.w;       // exclusive prefix of this lane's quad
        v.x += excl; v.y += excl; v.z += excl; v.w += excl;
        // conflict-free vector store of the scanned row
        *reinterpret_cast<float4*>(&sat[r * SAT_STRIDE + 4 + lane * 4]) = v;
        if (lane == 0) sat[r * SAT_STRIDE + 3] = 0.0f;   // x = -1 boundary
    }
    __syncthreads();

    // --- Phase 2: column prefix scan (threads 0..127, conflict-free) ---
    if (tid < WW) {
        float* p = &sat[4 + tid];
        float acc = 0.0f;
        #pragma unroll 8
        for (int y = 0; y < HH; y++) {
            acc += p[y * SAT_STRIDE];
            p[y * SAT_STRIDE] = acc;
        }
        // column 3 (zeros) needs no scan: stays zero.
    }
    __syncthreads();

    // --- Phase 3: gather, 4 LDS per patch ---
    for (int n = tid; n < N; n += 256) {
        int4 q = g_coords[n];                 // x0, y0, x1, y1  (clamped)
        int yb = max(q.w, 1) - 1;             // y1 - 1
        int ya = max(q.y, 1) - 1;             // y0 - 1
        float mbot  = (q.y > 0) ? 1.0f : 0.0f;
        float vmask = (q.z > q.x && q.w > q.y) ? 1.0f : 0.0f;
        const float* rb = &sat[yb * SAT_STRIDE + 3];
        const float* ra = &sat[ya * SAT_STRIDE + 3];
        float s = (rb[q.z] - rb[q.x]) - mbot * (ra[q.z] - ra[q.x]);
        out[(size_t)n * C + c] = s * vmask * g_inv[n];
    }
}

// ---------------------------------------------------------------------------
extern "C" void kernel_launch(void* const* d_in, const int* in_sizes, int n_in,
                              void* d_out, int out_size) {
    const float* fm  = (const float*)d_in[0];
    const float* roi = (const float*)d_in[1];
    float* out = (float*)d_out;

    int C     = in_sizes[0] / (HH * WW);
    int nrois = in_sizes[1] / 4;
    int N     = out_size / C;
    int patch_num = N / nrois;
    int p = (int)(sqrtf((float)patch_num) + 0.5f);

    coords_kernel<<<(N + 255) / 256, 256>>>(roi, nrois, patch_num, p);

    size_t smem = (size_t)HH * SAT_STRIDE * sizeof(float);
    cudaFuncSetAttribute(sat_pool_kernel,
                         cudaFuncAttributeMaxDynamicSharedMemorySize,
                         (int)smem);
    sat_pool_kernel<<<C, 256, smem>>>(fm, out, C, N);
}

// round 4
// speedup vs baseline: 1.0989x; 1.0989x over previous
#include <cuda_runtime.h>
#include <math.h>

#define HH 128
#define WW 128
#define SAT_STRIDE 132           // row stride in floats (mult of 4; data cols 4..131)
#define MAX_PATCH 8192

// Scratch (no allocations allowed): patch coords + reciprocal counts.
__device__ int4  g_coords[MAX_PATCH];
__device__ float g_inv[MAX_PATCH];

// ---------------------------------------------------------------------------
// Kernel 1: patch coordinates, exactly matching the reference's float math.
//   n = i * nrois + r ;  round == rintf (round-half-even == jnp.round)
// ---------------------------------------------------------------------------
__global__ void coords_kernel(const float* __restrict__ roi,
                              int nrois, int patch_num, int p) {
    int n = blockIdx.x * blockDim.x + threadIdx.x;
    int N = nrois * patch_num;
    if (n >= N) return;

    int i = n / nrois;     // patch index within roi
    int r = n % nrois;     // roi index

    float4 rb = reinterpret_cast<const float4*>(roi)[r];
    float xmin = rb.x, ymin = rb.y, xmax = rb.z, ymax = rb.w;

    float ix = (float)(i % p);
    float iy = (float)(i / p);
    float pf = (float)p;

    float wstep = __fdiv_rn(__fadd_rn(xmax, -xmin), pf);
    float hstep = __fdiv_rn(__fadd_rn(ymax, -ymin), pf);

    float ax = __fadd_rn(xmin, __fmul_rn(ix, wstep));
    float ay = __fadd_rn(ymin, __fmul_rn(iy, hstep));

    int x0 = (int)rintf(ax);
    int y0 = (int)rintf(ay);
    int x1 = (int)rintf(__fadd_rn(ax, wstep));
    int y1 = (int)rintf(__fadd_rn(ay, hstep));

    // Reference divides by the RAW (unclamped) count.
    float cnt = (float)((y1 - y0) * (x1 - x0));
    g_inv[n] = 1.0f / fmaxf(cnt, 1.0f);

    // Clamp only for safe SAT indexing.
    x0 = min(max(x0, 0), WW);  x1 = min(max(x1, 0), WW);
    y0 = min(max(y0, 0), HH);  y1 = min(max(y1, 0), HH);
    g_coords[n] = make_int4(x0, y0, x1, y1);
}

// ---------------------------------------------------------------------------
// Kernel 2: one CTA (256 thr) per channel.
//   Phase 0: bulk load plane -> smem (raw), 2 LDG.128/thread issued
//            back-to-back for max MLP, conflict-free STS.128.
//   Phase 1: row scan: warp per row (16 rows/warp), LDS.128 + intra-quad
//            scan + shfl_up warp scan + STS.128 (conflict-free).
//   Phase 2: column scan split 2-way: thread (half, col) scans 64 rows of
//            its column in place (lane stride 1 -> conflict-free).
//            Full SAT value: S[y][x] = part[y][x] + (y>=64)*part[63][x].
//   Phase 3: gather; half-stitch + y0==0 boundary handled by predication.
// ---------------------------------------------------------------------------
__global__ void __launch_bounds__(256) sat_pool_kernel(
    const float* __restrict__ fm, float* __restrict__ out, int C, int N) {
    extern __shared__ float sat[];   // HH * SAT_STRIDE floats = 67584 B

    const int c    = blockIdx.x;
    const int tid  = threadIdx.x;
    const int warp = tid >> 5;
    const int lane = tid & 31;

    // --- Phase 0: high-MLP bulk load into smem (raw) ---
    {
        const float4* src =
            reinterpret_cast<const float4*>(fm + (size_t)c * HH * WW);
        // j in {tid, tid+256}: row = j>>5 (warp-uniform), quad col = j&31
        float4 v0 = src[tid];
        float4 v1 = src[tid + 256];
        int r0 = tid >> 5,          q0 = tid & 31;
        int r1 = (tid + 256) >> 5,  q1 = tid & 31;
        #pragma unroll 1
        for (int k = tid + 512; k < (HH * WW) / 4; k += 512) {
            // (HH*WW/4 = 4096; loop runs 7 more pairs) -- handled below
            break;
        }
        // 4096 float4s total, 512 covered per pass -> 8 passes; unrolled:
        *reinterpret_cast<float4*>(&sat[r0 * SAT_STRIDE + 4 + q0 * 4]) = v0;
        *reinterpret_cast<float4*>(&sat[r1 * SAT_STRIDE + 4 + q1 * 4]) = v1;
        #pragma unroll
        for (int pass = 1; pass < 8; pass++) {
            int j0 = tid + pass * 512;
            int j1 = tid + pass * 512 + 256;
            float4 a = src[j0];
            float4 b = src[j1];
            *reinterpret_cast<float4*>(
                &sat[(j0 >> 5) * SAT_STRIDE + 4 + (j0 & 31) * 4]) = a;
            *reinterpret_cast<float4*>(
                &sat[(j1 >> 5) * SAT_STRIDE + 4 + (j1 & 31) * 4]) = b;
        }
        if (tid < HH) sat[tid * SAT_STRIDE + 3] = 0.0f;  // x = -1 boundary col
    }
    __syncthreads();

    // --- Phase 1: row prefix scan (warp per row, 16 rows/warp) ---
    #pragma unroll 4
    for (int r = warp; r < HH; r += 8) {
        float4 v = *reinterpret_cast<const float4*>(
            &sat[r * SAT_STRIDE + 4 + lane * 4]);
        v.y += v.x; v.z += v.y; v.w += v.z;          // intra-quad scan
        float s = v.w;
        #pragma unroll
        for (int d = 1; d < 32; d <<= 1) {           // warp scan of quad sums
            float t = __shfl_up_sync(0xffffffffu, s, d);
            if (lane >= d) s += t;
        }
        float excl = s - v.w;
        v.x += excl; v.y += excl; v.z += excl; v.w += excl;
        *reinterpret_cast<float4*>(&sat[r * SAT_STRIDE + 4 + lane * 4]) = v;
    }
    __syncthreads();

    // --- Phase 2: column scan, 2-way split over 256 threads ---
    {
        int col  = tid & 127;            // 0..127
        int half = tid >> 7;             // 0: rows 0..63, 1: rows 64..127
        float* p = &sat[(half * 64) * SAT_STRIDE + 4 + col];
        float acc = 0.0f;
        #pragma unroll 8
        for (int y = 0; y < 64; y++) {
            acc += p[y * SAT_STRIDE];
            p[y * SAT_STRIDE] = acc;
        }
    }
    __syncthreads();

    // --- Phase 3: gather (predicated half-stitch), write out ---
    const float* r63 = &sat[63 * SAT_STRIDE + 3];
    for (int n = tid; n < N; n += 256) {
        int4 q = g_coords[n];                 // x0, y0, x1, y1  (clamped)
        int yb = max(q.w, 1) - 1;             // y1 - 1
        int ya = max(q.y, 1) - 1;             // y0 - 1
        float mbot  = (q.y > 0) ? 1.0f : 0.0f;
        float vmask = (q.z > q.x && q.w > q.y) ? 1.0f : 0.0f;
        float d63 = r63[q.z] - r63[q.x];      // full S row 63 difference
        const float* rb = &sat[yb * SAT_STRIDE + 3];
        const float* ra = &sat[ya * SAT_STRIDE + 3];
        float sb = (rb[q.z] - rb[q.x]) + ((yb >= 64) ? d63 : 0.0f);
        float sa = (ra[q.z] - ra[q.x]) + ((ya >= 64) ? d63 : 0.0f);
        float s = sb - mbot * sa;
        out[(size_t)n * C + c] = s * vmask * g_inv[n];
    }
}

// ---------------------------------------------------------------------------
extern "C" void kernel_launch(void* const* d_in, const int* in_sizes, int n_in,
                              void* d_out, int out_size) {
    const float* fm  = (const float*)d_in[0];
    const float* roi = (const float*)d_in[1];
    float* out = (float*)d_out;

    int C     = in_sizes[0] / (HH * WW);
    int nrois = in_sizes[1] / 4;
    int N     = out_size / C;
    int patch_num = N / nrois;
    int p = (int)(sqrtf((float)patch_num) + 0.5f);

    coords_kernel<<<(N + 255) / 256, 256>>>(roi, nrois, patch_num, p);

    size_t smem = (size_t)HH * SAT_STRIDE * sizeof(float);
    cudaFuncSetAttribute(sat_pool_kernel,
                         cudaFuncAttributeMaxDynamicSharedMemorySize,
                         (int)smem);
    sat_pool_kernel<<<C, 256, smem>>>(fm, out, C, N);
}

// round 5
// speedup vs baseline: 1.2633x; 1.1497x over previous
#include <cuda_runtime.h>
#include <math.h>

#define HH 128
#define WW 128
#define SAT_STRIDE 132           // row stride in floats (mult of 4; data cols 4..131)
#define MAX_PATCH 8192

// Scratch (no allocations allowed): patch coords + reciprocal counts.
__device__ int4  g_coords[MAX_PATCH];
__device__ float g_inv[MAX_PATCH];

// ---------------------------------------------------------------------------
// Kernel 1: patch coordinates, exactly matching the reference's float math.
//   n = i * nrois + r ;  round == rintf (round-half-even == jnp.round)
// ---------------------------------------------------------------------------
__global__ void coords_kernel(const float* __restrict__ roi,
                              int nrois, int patch_num, int p) {
    int n = blockIdx.x * blockDim.x + threadIdx.x;
    int N = nrois * patch_num;
    if (n >= N) return;

    int i = n / nrois;     // patch index within roi
    int r = n % nrois;     // roi index

    float4 rb = reinterpret_cast<const float4*>(roi)[r];
    float xmin = rb.x, ymin = rb.y, xmax = rb.z, ymax = rb.w;

    float ix = (float)(i % p);
    float iy = (float)(i / p);
    float pf = (float)p;

    float wstep = __fdiv_rn(__fadd_rn(xmax, -xmin), pf);
    float hstep = __fdiv_rn(__fadd_rn(ymax, -ymin), pf);

    float ax = __fadd_rn(xmin, __fmul_rn(ix, wstep));
    float ay = __fadd_rn(ymin, __fmul_rn(iy, hstep));

    int x0 = (int)rintf(ax);
    int y0 = (int)rintf(ay);
    int x1 = (int)rintf(__fadd_rn(ax, wstep));
    int y1 = (int)rintf(__fadd_rn(ay, hstep));

    // Reference divides by the RAW (unclamped) count.
    float cnt = (float)((y1 - y0) * (x1 - x0));
    g_inv[n] = 1.0f / fmaxf(cnt, 1.0f);

    // Clamp only for safe SAT indexing.
    x0 = min(max(x0, 0), WW);  x1 = min(max(x1, 0), WW);
    y0 = min(max(y0, 0), HH);  y1 = min(max(y1, 0), HH);
    g_coords[n] = make_int4(x0, y0, x1, y1);
}

// ---------------------------------------------------------------------------
// Kernel 2: one CTA (256 thr, 3 CTAs/SM) per channel.
//   Phase 0+1 fused: warp owns 16 rows, processed in 2 batches of 8.
//     Batch: 8 LDG.128 issued back-to-back (high MLP), then 8 independent
//     register scans (intra-quad + shfl_up, ILP across rows), then 8
//     conflict-free STS.128 of the scanned rows. Raw data never touches
//     smem -> saves 128 KB of smem traffic per CTA vs. the decoupled form.
//   Phase 2: column scan split 2-way (thread (half, col) scans 64 rows,
//     stride-1 across lanes -> conflict-free).
//     Full SAT: S[y][x] = part[y][x] + (y>=64)*part[63][x].
//   Phase 3: gather; half-stitch + y0==0 boundary by predication.
// ---------------------------------------------------------------------------
__global__ void __launch_bounds__(256, 3) sat_pool_kernel(
    const float* __restrict__ fm, float* __restrict__ out, int C, int N) {
    extern __shared__ float sat[];   // HH * SAT_STRIDE floats = 67584 B

    const int c    = blockIdx.x;
    const int tid  = threadIdx.x;
    const int warp = tid >> 5;
    const int lane = tid & 31;

    // --- Phase 0+1: fused high-MLP load + row prefix scan ---
    const float4* src =
        reinterpret_cast<const float4*>(fm + (size_t)c * HH * WW);
    #pragma unroll
    for (int half = 0; half < 2; half++) {
        const int rbase = warp * 16 + half * 8;
        float4 v[8];
        #pragma unroll
        for (int k = 0; k < 8; k++)               // 8 LDGs in flight
            v[k] = src[(rbase + k) * (WW / 4) + lane];
        #pragma unroll
        for (int k = 0; k < 8; k++) {             // 8 independent scan chains
            float4 t = v[k];
            t.y += t.x; t.z += t.y; t.w += t.z;   // intra-quad scan
            float s = t.w;
            #pragma unroll
            for (int d = 1; d < 32; d <<= 1) {    // warp scan of quad sums
                float u = __shfl_up_sync(0xffffffffu, s, d);
                if (lane >= d) s += u;
            }
            float excl = s - t.w;
            t.x += excl; t.y += excl; t.z += excl; t.w += excl;
            *reinterpret_cast<float4*>(
                &sat[(rbase + k) * SAT_STRIDE + 4 + lane * 4]) = t;
        }
    }
    if (tid < HH) sat[tid * SAT_STRIDE + 3] = 0.0f;   // x = -1 boundary col
    __syncthreads();

    // --- Phase 2: column scan, 2-way split over 256 threads ---
    {
        int col  = tid & 127;            // 0..127
        int half = tid >> 7;             // 0: rows 0..63, 1: rows 64..127
        float* p = &sat[(half * 64) * SAT_STRIDE + 4 + col];
        float acc = 0.0f;
        #pragma unroll 8
        for (int y = 0; y < 64; y++) {
            acc += p[y * SAT_STRIDE];
            p[y * SAT_STRIDE] = acc;
        }
    }
    __syncthreads();

    // --- Phase 3: gather (predicated half-stitch), write out ---
    const float* r63 = &sat[63 * SAT_STRIDE + 3];
    for (int n = tid; n < N; n += 256) {
        int4 q = g_coords[n];                 // x0, y0, x1, y1  (clamped)
        int yb = max(q.w, 1) - 1;             // y1 - 1
        int ya = max(q.y, 1) - 1;             // y0 - 1
        float mbot  = (q.y > 0) ? 1.0f : 0.0f;
        float vmask = (q.z > q.x && q.w > q.y) ? 1.0f : 0.0f;
        float d63 = r63[q.z] - r63[q.x];      // full S row-63 difference
        const float* rb = &sat[yb * SAT_STRIDE + 3];
        const float* ra = &sat[ya * SAT_STRIDE + 3];
        float sb = (rb[q.z] - rb[q.x]) + ((yb >= 64) ? d63 : 0.0f);
        float sa = (ra[q.z] - ra[q.x]) + ((ya >= 64) ? d63 : 0.0f);
        float s = sb - mbot * sa;
        out[(size_t)n * C + c] = s * vmask * g_inv[n];
    }
}

// ---------------------------------------------------------------------------
extern "C" void kernel_launch(void* const* d_in, const int* in_sizes, int n_in,
                              void* d_out, int out_size) {
    const float* fm  = (const float*)d_in[0];
    const float* roi = (const float*)d_in[1];
    float* out = (float*)d_out;

    int C     = in_sizes[0] / (HH * WW);
    int nrois = in_sizes[1] / 4;
    int N     = out_size / C;
    int patch_num = N / nrois;
    int p = (int)(sqrtf((float)patch_num) + 0.5f);

    coords_kernel<<<(N + 255) / 256, 256>>>(roi, nrois, patch_num, p);

    size_t smem = (size_t)HH * SAT_STRIDE * sizeof(float);
    cudaFuncSetAttribute(sat_pool_kernel,
                         cudaFuncAttributeMaxDynamicSharedMemorySize,
                         (int)smem);
    sat_pool_kernel<<<C, 256, smem>>>(fm, out, C, N);
}

// round 7
// speedup vs baseline: 1.3089x; 1.0361x over previous
#include <cuda_runtime.h>
#include <math.h>

#define HH 128
#define WW 128
#define SAT_STRIDE 132           // row stride in floats (mult of 4; data cols 4..131)
#define MAX_PATCH 8192
#define MAX_C 2048

// Scratch (no allocations allowed).
__device__ int4  g_coords[MAX_PATCH];
__device__ float g_inv[MAX_PATCH];
__device__ float g_outT[(size_t)MAX_C * MAX_PATCH];   // [C][N] transposed output

// ---------------------------------------------------------------------------
// Kernel 1: patch coordinates, exactly matching the reference's float math.
//   n = i * nrois + r ;  round == rintf (round-half-even == jnp.round)
// ---------------------------------------------------------------------------
__global__ void coords_kernel(const float* __restrict__ roi,
                              int nrois, int patch_num, int p) {
    int n = blockIdx.x * blockDim.x + threadIdx.x;
    int N = nrois * patch_num;
    if (n >= N) return;

    int i = n / nrois;     // patch index within roi
    int r = n % nrois;     // roi index

    float4 rb = reinterpret_cast<const float4*>(roi)[r];
    float xmin = rb.x, ymin = rb.y, xmax = rb.z, ymax = rb.w;

    float ix = (float)(i % p);
    float iy = (float)(i / p);
    float pf = (float)p;

    float wstep = __fdiv_rn(__fadd_rn(xmax, -xmin), pf);
    float hstep = __fdiv_rn(__fadd_rn(ymax, -ymin), pf);

    float ax = __fadd_rn(xmin, __fmul_rn(ix, wstep));
    float ay = __fadd_rn(ymin, __fmul_rn(iy, hstep));

    int x0 = (int)rintf(ax);
    int y0 = (int)rintf(ay);
    int x1 = (int)rintf(__fadd_rn(ax, wstep));
    int y1 = (int)rintf(__fadd_rn(ay, hstep));

    // Reference divides by the RAW (unclamped) count.
    float cnt = (float)((y1 - y0) * (x1 - x0));
    g_inv[n] = 1.0f / fmaxf(cnt, 1.0f);

    // Clamp only for safe SAT indexing.
    x0 = min(max(x0, 0), WW);  x1 = min(max(x1, 0), WW);
    y0 = min(max(y0, 0), HH);  y1 = min(max(y1, 0), HH);
    g_coords[n] = make_int4(x0, y0, x1, y1);
}

// ---------------------------------------------------------------------------
// Kernel 2: one CTA (256 thr, 3 CTAs/SM) per channel. Writes TRANSPOSED
// output g_outT[c][n] so stores are coalesced (STG.128, 4 patches/thread).
// ---------------------------------------------------------------------------
__global__ void __launch_bounds__(256, 3) sat_pool_kernel(
    const float* __restrict__ fm, int C, int N) {
    extern __shared__ float sat[];   // HH * SAT_STRIDE floats = 67584 B

    const int c    = blockIdx.x;
    const int tid  = threadIdx.x;
    const int warp = tid >> 5;
    const int lane = tid & 31;

    // --- Phase 0+1: fused high-MLP load + row prefix scan ---
    const float4* src =
        reinterpret_cast<const float4*>(fm + (size_t)c * HH * WW);
    #pragma unroll
    for (int half = 0; half < 2; half++) {
        const int rbase = warp * 16 + half * 8;
        float4 v[8];
        #pragma unroll
        for (int k = 0; k < 8; k++)               // 8 LDGs in flight
            v[k] = src[(rbase + k) * (WW / 4) + lane];
        #pragma unroll
        for (int k = 0; k < 8; k++) {             // 8 independent scan chains
            float4 t = v[k];
            t.y += t.x; t.z += t.y; t.w += t.z;   // intra-quad scan
            float s = t.w;
            #pragma unroll
            for (int d = 1; d < 32; d <<= 1) {    // warp scan of quad sums
                float u = __shfl_up_sync(0xffffffffu, s, d);
                if (lane >= d) s += u;
            }
            float excl = s - t.w;
            t.x += excl; t.y += excl; t.z += excl; t.w += excl;
            *reinterpret_cast<float4*>(
                &sat[(rbase + k) * SAT_STRIDE + 4 + lane * 4]) = t;
        }
    }
    if (tid < HH) sat[tid * SAT_STRIDE + 3] = 0.0f;   // x = -1 boundary col
    __syncthreads();

    // --- Phase 2: column scan, 2-way split over 256 threads ---
    {
        int col  = tid & 127;            // 0..127
        int half = tid >> 7;             // 0: rows 0..63, 1: rows 64..127
        float* p = &sat[(half * 64) * SAT_STRIDE + 4 + col];
        float acc = 0.0f;
        #pragma unroll 8
        for (int y = 0; y < 64; y++) {
            acc += p[y * SAT_STRIDE];
            p[y * SAT_STRIDE] = acc;
        }
    }
    __syncthreads();

    // --- Phase 3: gather, 4 patches/thread, one coalesced STG.128 ---
    const float* r63 = &sat[63 * SAT_STRIDE + 3];
    float* orow = &g_outT[(size_t)c * N];
    if ((N & 3) == 0) {
        for (int n4 = tid * 4; n4 < N; n4 += 1024) {
            float res[4];
            #pragma unroll
            for (int k = 0; k < 4; k++) {
                int4 q = g_coords[n4 + k];        // x0, y0, x1, y1 (clamped)
                int yb = max(q.w, 1) - 1;
                int ya = max(q.y, 1) - 1;
                float mbot  = (q.y > 0) ? 1.0f : 0.0f;
                float vmask = (q.z > q.x && q.w > q.y) ? 1.0f : 0.0f;
                float d63 = r63[q.z] - r63[q.x];
                const float* rb = &sat[yb * SAT_STRIDE + 3];
                const float* ra = &sat[ya * SAT_STRIDE + 3];
                float sb = (rb[q.z] - rb[q.x]) + ((yb >= 64) ? d63 : 0.0f);
                float sa = (ra[q.z] - ra[q.x]) + ((ya >= 64) ? d63 : 0.0f);
                res[k] = (sb - mbot * sa) * vmask * g_inv[n4 + k];
            }
            *reinterpret_cast<float4*>(&orow[n4]) =
                make_float4(res[0], res[1], res[2], res[3]);
        }
    } else {
        for (int n = tid; n < N; n += 256) {
            int4 q = g_coords[n];
            int yb = max(q.w, 1) - 1;
            int ya = max(q.y, 1) - 1;
            float mbot  = (q.y > 0) ? 1.0f : 0.0f;
            float vmask = (q.z > q.x && q.w > q.y) ? 1.0f : 0.0f;
            float d63 = r63[q.z] - r63[q.x];
            const float* rb = &sat[yb * SAT_STRIDE + 3];
            const float* ra = &sat[ya * SAT_STRIDE + 3];
            float sb = (rb[q.z] - rb[q.x]) + ((yb >= 64) ? d63 : 0.0f);
            float sa = (ra[q.z] - ra[q.x]) + ((ya >= 64) ? d63 : 0.0f);
            orow[n] = (sb - mbot * sa) * vmask * g_inv[n];
        }
    }
}

// ---------------------------------------------------------------------------
// Kernel 3: tiled transpose g_outT[C][N] -> out[N][C]. Coalesced both ways.
// ---------------------------------------------------------------------------
__global__ void __launch_bounds__(256) transpose_kernel(
    float* __restrict__ out, int C, int N) {
    __shared__ float tile[32][33];
    int nBase = blockIdx.x * 32;
    int cBase = blockIdx.y * 32;
    int tx = threadIdx.x;          // 0..31
    int ty = threadIdx.y;          // 0..7

    #pragma unroll
    for (int k = 0; k < 32; k += 8) {
        int cc = cBase + ty + k, nn = nBase + tx;
        if (cc < C && nn < N)
            tile[ty + k][tx] = g_outT[(size_t)cc * N + nn];
    }
    __syncthreads();
    #pragma unroll
    for (int k = 0; k < 32; k += 8) {
        int nn = nBase + ty + k, cc = cBase + tx;
        if (nn < N && cc < C)
            out[(size_t)nn * C + cc] = tile[tx][ty + k];
    }
}

// ---------------------------------------------------------------------------
extern "C" void kernel_launch(void* const* d_in, const int* in_sizes, int n_in,
                              void* d_out, int out_size) {
    const float* fm  = (const float*)d_in[0];
    const float* roi = (const float*)d_in[1];
    float* out = (float*)d_out;

    int C     = in_sizes[0] / (HH * WW);
    int nrois = in_sizes[1] / 4;
    int N     = out_size / C;
    int patch_num = N / nrois;
    int p = (int)(sqrtf((float)patch_num) + 0.5f);

    coords_kernel<<<(N + 255) / 256, 256>>>(roi, nrois, patch_num, p);

    size_t smem = (size_t)HH * SAT_STRIDE * sizeof(float);
    cudaFuncSetAttribute(sat_pool_kernel,
                         cudaFuncAttributeMaxDynamicSharedMemorySize,
                         (int)smem);
    sat_pool_kernel<<<C, 256, smem>>>(fm, C, N);

    dim3 tgrid((N + 31) / 32, (C + 31) / 32);
    transpose_kernel<<<tgrid, dim3(32, 8)>>>(out, C, N);
}

// round 8
// speedup vs baseline: 1.3802x; 1.0545x over previous
#include <cuda_runtime.h>
#include <math.h>

#define HH 128
#define WW 128
#define SAT_STRIDE 132           // row stride in floats (mult of 4; data cols 4..131)
#define MAX_PATCH 8192
#define MAX_C 2048

// Scratch (no allocations allowed).
__device__ float g_outT[(size_t)MAX_C * MAX_PATCH];   // [C][N] transposed output

// ---------------------------------------------------------------------------
// Inline patch-coordinate math, bit-exact vs. the reference:
//   n = i * nrois + r ;  round == rintf (round-half-even == jnp.round)
// Returns clamped coords in q, raw-count reciprocal in inv.
// ---------------------------------------------------------------------------
__device__ __forceinline__ void patch_coords(
    const float4* __restrict__ roi4, int n, int nrois, int p,
    int4& q, float& inv) {
    int i = n / nrois;     // patch index within roi
    int r = n - i * nrois; // roi index

    float4 rb = roi4[r];
    float xmin = rb.x, ymin = rb.y, xmax = rb.z, ymax = rb.w;

    float ix = (float)(i % p);
    float iy = (float)(i / p);
    float pf = (float)p;

    float wstep = __fdiv_rn(__fadd_rn(xmax, -xmin), pf);
    float hstep = __fdiv_rn(__fadd_rn(ymax, -ymin), pf);

    float ax = __fadd_rn(xmin, __fmul_rn(ix, wstep));
    float ay = __fadd_rn(ymin, __fmul_rn(iy, hstep));

    int x0 = (int)rintf(ax);
    int y0 = (int)rintf(ay);
    int x1 = (int)rintf(__fadd_rn(ax, wstep));
    int y1 = (int)rintf(__fadd_rn(ay, hstep));

    // Reference divides by the RAW (unclamped) count.
    float cnt = (float)((y1 - y0) * (x1 - x0));
    inv = 1.0f / fmaxf(cnt, 1.0f);

    // Clamp only for safe SAT indexing.
    x0 = min(max(x0, 0), WW);  x1 = min(max(x1, 0), WW);
    y0 = min(max(y0, 0), HH);  y1 = min(max(y1, 0), HH);
    q = make_int4(x0, y0, x1, y1);
}

// ---------------------------------------------------------------------------
// One CTA (256 thr, 3 CTAs/SM) per channel. Writes TRANSPOSED output
// g_outT[c][n] so stores are coalesced (STG.128, 4 patches/thread).
// Coords are recomputed inline per thread (cheap ALU, deletes a whole
// serialized kernel launch from the critical path).
// ---------------------------------------------------------------------------
__global__ void __launch_bounds__(256, 3) sat_pool_kernel(
    const float* __restrict__ fm, const float* __restrict__ roi,
    int C, int N, int nrois, int p) {
    extern __shared__ float sat[];   // HH * SAT_STRIDE floats = 67584 B

    const int c    = blockIdx.x;
    const int tid  = threadIdx.x;
    const int warp = tid >> 5;
    const int lane = tid & 31;

    // --- Phase 0+1: fused high-MLP load + row prefix scan ---
    const float4* src =
        reinterpret_cast<const float4*>(fm + (size_t)c * HH * WW);
    #pragma unroll
    for (int half = 0; half < 2; half++) {
        const int rbase = warp * 16 + half * 8;
        float4 v[8];
        #pragma unroll
        for (int k = 0; k < 8; k++)               // 8 LDGs in flight
            v[k] = src[(rbase + k) * (WW / 4) + lane];
        #pragma unroll
        for (int k = 0; k < 8; k++) {             // 8 independent scan chains
            float4 t = v[k];
            t.y += t.x; t.z += t.y; t.w += t.z;   // intra-quad scan
            float s = t.w;
            #pragma unroll
            for (int d = 1; d < 32; d <<= 1) {    // warp scan of quad sums
                float u = __shfl_up_sync(0xffffffffu, s, d);
                if (lane >= d) s += u;
            }
            float excl = s - t.w;
            t.x += excl; t.y += excl; t.z += excl; t.w += excl;
            *reinterpret_cast<float4*>(
                &sat[(rbase + k) * SAT_STRIDE + 4 + lane * 4]) = t;
        }
    }
    if (tid < HH) sat[tid * SAT_STRIDE + 3] = 0.0f;   // x = -1 boundary col
    __syncthreads();

    // --- Phase 2: column scan, 2-way split over 256 threads ---
    {
        int col  = tid & 127;            // 0..127
        int half = tid >> 7;             // 0: rows 0..63, 1: rows 64..127
        float* ptr = &sat[(half * 64) * SAT_STRIDE + 4 + col];
        float acc = 0.0f;
        #pragma unroll 8
        for (int y = 0; y < 64; y++) {
            acc += ptr[y * SAT_STRIDE];
            ptr[y * SAT_STRIDE] = acc;
        }
    }
    __syncthreads();

    // --- Phase 3: gather with inline coords, coalesced STG.128 ---
    const float4* roi4 = reinterpret_cast<const float4*>(roi);
    const float* r63 = &sat[63 * SAT_STRIDE + 3];
    float* orow = &g_outT[(size_t)c * N];
    if ((N & 3) == 0) {
        for (int n4 = tid * 4; n4 < N; n4 += 1024) {
            float res[4];
            #pragma unroll
            for (int k = 0; k < 4; k++) {
                int4 q; float inv;
                patch_coords(roi4, n4 + k, nrois, p, q, inv);
                int yb = max(q.w, 1) - 1;
                int ya = max(q.y, 1) - 1;
                float mbot  = (q.y > 0) ? 1.0f : 0.0f;
                float vmask = (q.z > q.x && q.w > q.y) ? 1.0f : 0.0f;
                float d63 = r63[q.z] - r63[q.x];
                const float* rb = &sat[yb * SAT_STRIDE + 3];
                const float* ra = &sat[ya * SAT_STRIDE + 3];
                float sb = (rb[q.z] - rb[q.x]) + ((yb >= 64) ? d63 : 0.0f);
                float sa = (ra[q.z] - ra[q.x]) + ((ya >= 64) ? d63 : 0.0f);
                res[k] = (sb - mbot * sa) * vmask * inv;
            }
            *reinterpret_cast<float4*>(&orow[n4]) =
                make_float4(res[0], res[1], res[2], res[3]);
        }
    } else {
        for (int n = tid; n < N; n += 256) {
            int4 q; float inv;
            patch_coords(roi4, n, nrois, p, q, inv);
            int yb = max(q.w, 1) - 1;
            int ya = max(q.y, 1) - 1;
            float mbot  = (q.y > 0) ? 1.0f : 0.0f;
            float vmask = (q.z > q.x && q.w > q.y) ? 1.0f : 0.0f;
            float d63 = r63[q.z] - r63[q.x];
            const float* rb = &sat[yb * SAT_STRIDE + 3];
            const float* ra = &sat[ya * SAT_STRIDE + 3];
            float sb = (rb[q.z] - rb[q.x]) + ((yb >= 64) ? d63 : 0.0f);
            float sa = (ra[q.z] - ra[q.x]) + ((ya >= 64) ? d63 : 0.0f);
            orow[n] = (sb - mbot * sa) * vmask * inv;
        }
    }
}

// ---------------------------------------------------------------------------
// Tiled transpose g_outT[C][N] -> out[N][C]. Coalesced both ways.
// ---------------------------------------------------------------------------
__global__ void __launch_bounds__(256) transpose_kernel(
    float* __restrict__ out, int C, int N) {
    __shared__ float tile[32][33];
    int nBase = blockIdx.x * 32;
    int cBase = blockIdx.y * 32;
    int tx = threadIdx.x;          // 0..31
    int ty = threadIdx.y;          // 0..7

    #pragma unroll
    for (int k = 0; k < 32; k += 8) {
        int cc = cBase + ty + k, nn = nBase + tx;
        if (cc < C && nn < N)
            tile[ty + k][tx] = g_outT[(size_t)cc * N + nn];
    }
    __syncthreads();
    #pragma unroll
    for (int k = 0; k < 32; k += 8) {
        int nn = nBase + ty + k, cc = cBase + tx;
        if (nn < N && cc < C)
            out[(size_t)nn * C + cc] = tile[tx][ty + k];
    }
}

// ---------------------------------------------------------------------------
extern "C" void kernel_launch(void* const* d_in, const int* in_sizes, int n_in,
                              void* d_out, int out_size) {
    const float* fm  = (const float*)d_in[0];
    const float* roi = (const float*)d_in[1];
    float* out = (float*)d_out;

    int C     = in_sizes[0] / (HH * WW);
    int nrois = in_sizes[1] / 4;
    int N     = out_size / C;
    int patch_num = N / nrois;
    int p = (int)(sqrtf((float)patch_num) + 0.5f);

    size_t smem = (size_t)HH * SAT_STRIDE * sizeof(float);
    cudaFuncSetAttribute(sat_pool_kernel,
                         cudaFuncAttributeMaxDynamicSharedMemorySize,
                         (int)smem);
    sat_pool_kernel<<<C, 256, smem>>>(fm, roi, C, N, nrois, p);

    dim3 tgrid((N + 31) / 32, (C + 31) / 32);
    transpose_kernel<<<tgrid, dim3(32, 8)>>>(out, C, N);
}

// round 11
// speedup vs baseline: 1.3997x; 1.0141x over previous
#include <cuda_runtime.h>
#include <math.h>

#define HH 128
#define WW 128
#define SAT_STRIDE 132           // row stride in floats (mult of 4; data cols 4..131)
#define MAX_PATCH 8192
#define MAX_C 2048

// Scratch (no allocations allowed).
__device__ float g_outT[(size_t)MAX_C * MAX_PATCH];   // [C][N] transposed output

// ---------------------------------------------------------------------------
// Inline patch-coordinate math, bit-exact vs. the reference:
//   n = i * nrois + r ;  round == rintf (round-half-even == jnp.round)
// Returns clamped coords in q, raw-count reciprocal in inv.
// ---------------------------------------------------------------------------
__device__ __forceinline__ void patch_coords(
    const float4* __restrict__ roi4, int n, int nrois, int p,
    int4& q, float& inv) {
    int i = n / nrois;     // patch index within roi
    int r = n - i * nrois; // roi index

    float4 rb = roi4[r];
    float xmin = rb.x, ymin = rb.y, xmax = rb.z, ymax = rb.w;

    float ix = (float)(i % p);
    float iy = (float)(i / p);
    float pf = (float)p;

    float wstep = __fdiv_rn(__fadd_rn(xmax, -xmin), pf);
    float hstep = __fdiv_rn(__fadd_rn(ymax, -ymin), pf);

    float ax = __fadd_rn(xmin, __fmul_rn(ix, wstep));
    float ay = __fadd_rn(ymin, __fmul_rn(iy, hstep));

    int x0 = (int)rintf(ax);
    int y0 = (int)rintf(ay);
    int x1 = (int)rintf(__fadd_rn(ax, wstep));
    int y1 = (int)rintf(__fadd_rn(ay, hstep));

    // Reference divides by the RAW (unclamped) count.
    float cnt = (float)((y1 - y0) * (x1 - x0));
    inv = 1.0f / fmaxf(cnt, 1.0f);

    // Clamp only for safe SAT indexing.
    x0 = min(max(x0, 0), WW);  x1 = min(max(x1, 0), WW);
    y0 = min(max(y0, 0), HH);  y1 = min(max(y1, 0), HH);
    q = make_int4(x0, y0, x1, y1);
}

// ---------------------------------------------------------------------------
// One CTA (256 thr, 3 CTAs/SM) per channel. Writes TRANSPOSED output
// g_outT[c][n] so stores are coalesced (STG.128, 4 patches/thread).
// ---------------------------------------------------------------------------
__global__ void __launch_bounds__(256, 3) sat_pool_kernel(
    const float* __restrict__ fm, const float* __restrict__ roi,
    int C, int N, int nrois, int p) {
    extern __shared__ float sat[];   // HH * SAT_STRIDE floats = 67584 B

    const int c    = blockIdx.x;
    const int tid  = threadIdx.x;
    const int warp = tid >> 5;
    const int lane = tid & 31;

    // --- Phase 0+1: fused high-MLP load + row prefix scan ---
    const float4* src =
        reinterpret_cast<const float4*>(fm + (size_t)c * HH * WW);
    #pragma unroll
    for (int half = 0; half < 2; half++) {
        const int rbase = warp * 16 + half * 8;
        float4 v[8];
        #pragma unroll
        for (int k = 0; k < 8; k++)               // 8 LDGs in flight
            v[k] = src[(rbase + k) * (WW / 4) + lane];
        #pragma unroll
        for (int k = 0; k < 8; k++) {             // 8 independent scan chains
            float4 t = v[k];
            t.y += t.x; t.z += t.y; t.w += t.z;   // intra-quad scan
            float s = t.w;
            #pragma unroll
            for (int d = 1; d < 32; d <<= 1) {    // warp scan of quad sums
                float u = __shfl_up_sync(0xffffffffu, s, d);
                if (lane >= d) s += u;
            }
            float excl = s - t.w;
            t.x += excl; t.y += excl; t.z += excl; t.w += excl;
            *reinterpret_cast<float4*>(
                &sat[(rbase + k) * SAT_STRIDE + 4 + lane * 4]) = t;
        }
    }
    if (tid < HH) sat[tid * SAT_STRIDE + 3] = 0.0f;   // x = -1 boundary col
    __syncthreads();

    // --- Phase 2: column scan, 2-way split over 256 threads ---
    {
        int col  = tid & 127;            // 0..127
        int half = tid >> 7;             // 0: rows 0..63, 1: rows 64..127
        float* ptr = &sat[(half * 64) * SAT_STRIDE + 4 + col];
        float acc = 0.0f;
        #pragma unroll 8
        for (int y = 0; y < 64; y++) {
            acc += ptr[y * SAT_STRIDE];
            ptr[y * SAT_STRIDE] = acc;
        }
    }
    __syncthreads();

    // --- Phase 3: gather with inline coords, coalesced STG.128 ---
    const float4* roi4 = reinterpret_cast<const float4*>(roi);
    const float* r63 = &sat[63 * SAT_STRIDE + 3];
    float* orow = &g_outT[(size_t)c * N];
    if ((N & 3) == 0) {
        for (int n4 = tid * 4; n4 < N; n4 += 1024) {
            float res[4];
            #pragma unroll
            for (int k = 0; k < 4; k++) {
                int4 q; float inv;
                patch_coords(roi4, n4 + k, nrois, p, q, inv);
                int yb = max(q.w, 1) - 1;
                int ya = max(q.y, 1) - 1;
                float mbot  = (q.y > 0) ? 1.0f : 0.0f;
                float vmask = (q.z > q.x && q.w > q.y) ? 1.0f : 0.0f;
                float d63 = r63[q.z] - r63[q.x];
                const float* rb = &sat[yb * SAT_STRIDE + 3];
                const float* ra = &sat[ya * SAT_STRIDE + 3];
                float sb = (rb[q.z] - rb[q.x]) + ((yb >= 64) ? d63 : 0.0f);
                float sa = (ra[q.z] - ra[q.x]) + ((ya >= 64) ? d63 : 0.0f);
                res[k] = (sb - mbot * sa) * vmask * inv;
            }
            *reinterpret_cast<float4*>(&orow[n4]) =
                make_float4(res[0], res[1], res[2], res[3]);
        }
    } else {
        for (int n = tid; n < N; n += 256) {
            int4 q; float inv;
            patch_coords(roi4, n, nrois, p, q, inv);
            int yb = max(q.w, 1) - 1;
            int ya = max(q.y, 1) - 1;
            float mbot  = (q.y > 0) ? 1.0f : 0.0f;
            float vmask = (q.z > q.x && q.w > q.y) ? 1.0f : 0.0f;
            float d63 = r63[q.z] - r63[q.x];
            const float* rb = &sat[yb * SAT_STRIDE + 3];
            const float* ra = &sat[ya * SAT_STRIDE + 3];
            float sb = (rb[q.z] - rb[q.x]) + ((yb >= 64) ? d63 : 0.0f);
            float sa = (ra[q.z] - ra[q.x]) + ((ya >= 64) ? d63 : 0.0f);
            orow[n] = (sb - mbot * sa) * vmask * inv;
        }
    }
}

// ---------------------------------------------------------------------------
// Tiled transpose g_outT[C][N] -> out[N][C], 64x64 tiles, float4 on both
// global sides (4x LDG.128 + 4x STG.128 per thread = 128 B/thread).
// Requires 64 | N and 64 | C (fallback path otherwise).
// ---------------------------------------------------------------------------
__global__ void __launch_bounds__(256) transpose64_kernel(
    float* __restrict__ out, int C, int N) {
    __shared__ float tile[64][65];
    const int nBase = blockIdx.x * 64;
    const int cBase = blockIdx.y * 64;
    const int tid = threadIdx.x;

    // Load: rows = channels. thread -> (cl = tid>>4, quad n4 = tid&15).
    {
        const int n4 = (tid & 15) * 4;
        const int cl = tid >> 4;            // 0..15
        #pragma unroll
        for (int k = 0; k < 4; k++) {
            int cc = cl + k * 16;           // 0..63
            float4 v = *reinterpret_cast<const float4*>(
                &g_outT[(size_t)(cBase + cc) * N + nBase + n4]);
            tile[cc][n4 + 0] = v.x;
            tile[cc][n4 + 1] = v.y;
            tile[cc][n4 + 2] = v.z;
            tile[cc][n4 + 3] = v.w;
        }
    }
    __syncthreads();

    // Store: rows = patches. thread -> (nl = tid>>4, quad c4 = tid&15).
    {
        const int c4 = (tid & 15) * 4;
        const int nl = tid >> 4;            // 0..15
        #pragma unroll
        for (int k = 0; k < 4; k++) {
            int nn = nl + k * 16;           // 0..63
            float4 v = make_float4(tile[c4 + 0][nn], tile[c4 + 1][nn],
                                   tile[c4 + 2][nn], tile[c4 + 3][nn]);
            *reinterpret_cast<float4*>(
                &out[(size_t)(nBase + nn) * C + cBase + c4]) = v;
        }
    }
}

// Fallback for non-multiple-of-64 shapes (not hit for this problem).
__global__ void __launch_bounds__(256) transpose32_kernel(
    float* __restrict__ out, int C, int N) {
    __shared__ float tile[32][33];
    int nBase = blockIdx.x * 32;
    int cBase = blockIdx.y * 32;
    int tx = threadIdx.x & 31;
    int ty = threadIdx.x >> 5;   // 0..7
    #pragma unroll
    for (int k = 0; k < 32; k += 8) {
        int cc = cBase + ty + k, nn = nBase + tx;
        if (cc < C && nn < N)
            tile[ty + k][tx] = g_outT[(size_t)cc * N + nn];
    }
    __syncthreads();
    #pragma unroll
    for (int k = 0; k < 32; k += 8) {
        int nn = nBase + ty + k, cc = cBase + tx;
        if (nn < N && cc < C)
            out[(size_t)nn * C + cc] = tile[tx][ty + k];
    }
}

// ---------------------------------------------------------------------------
extern "C" void kernel_launch(void* const* d_in, const int* in_sizes, int n_in,
                              void* d_out, int out_size) {
    const float* fm  = (const float*)d_in[0];
    const float* roi = (const float*)d_in[1];
    float* out = (float*)d_out;

    int C     = in_sizes[0] / (HH * WW);
    int nrois = in_sizes[1] / 4;
    int N     = out_size / C;
    int patch_num = N / nrois;
    int p = (int)(sqrtf((float)patch_num) + 0.5f);

    size_t smem = (size_t)HH * SAT_STRIDE * sizeof(float);
    cudaFuncSetAttribute(sat_pool_kernel,
                         cudaFuncAttributeMaxDynamicSharedMemorySize,
                         (int)smem);
    sat_pool_kernel<<<C, 256, smem>>>(fm, roi, C, N, nrois, p);

    if ((N % 64 == 0) && (C % 64 == 0)) {
        dim3 tgrid(N / 64, C / 64);
        transpose64_kernel<<<tgrid, 256>>>(out, C, N);
    } else {
        dim3 tgrid((N + 31) / 32, (C + 31) / 32);
        transpose32_kernel<<<tgrid, 256>>>(out, C, N);
    }
}